// round 1
// baseline (speedup 1.0000x reference)
#include <cuda_runtime.h>

// Problem constants (IN = OUT = 4096, P = D = 4096)
#define NP 4096
#define KTOP 3687.0f       // ceil(int(0.9*4096*4096)/4096)
#define INV_LR 100.0f      // 1 / 0.01
#define NUM_ITER 50

// Scratch (device globals: allocation-free per harness rules)
__device__ float g_mask[NP];
__device__ float g_W[(size_t)4096 * 4096];   // W[r][j] = mask[(r-j)&4095] * V[(r-j)&4095][j]

// ---------------------------------------------------------------------------
// Kernel 1: Dykstra soft-top-k mask. One block, 1024 threads, 4 elems/thread.
// ---------------------------------------------------------------------------
__global__ __launch_bounds__(1024) void dykstra_kernel(const float* __restrict__ alpha) {
    __shared__ float red[32];
    __shared__ float total_sh;
    int tid = threadIdx.x;

    float x[4], p[4], q[4];
#pragma unroll
    for (int e = 0; e < 4; e++) {
        float s = alpha[tid * 4 + e] * INV_LR;
        x[e] = s; p[e] = 0.f; q[e] = 0.f;
    }

    for (int it = 0; it < NUM_ITER; it++) {
        float t[4];
        float local = 0.f;
#pragma unroll
        for (int e = 0; e < 4; e++) { t[e] = x[e] + p[e]; local += t[e]; }

        // block reduction of sum(t)
#pragma unroll
        for (int o = 16; o > 0; o >>= 1) local += __shfl_xor_sync(0xffffffffu, local, o);
        if ((tid & 31) == 0) red[tid >> 5] = local;
        __syncthreads();
        if (tid < 32) {
            float v = red[tid];
#pragma unroll
            for (int o = 16; o > 0; o >>= 1) v += __shfl_xor_sync(0xffffffffu, v, o);
            if (tid == 0) total_sh = v;
        }
        __syncthreads();
        float shift = (KTOP - total_sh) * (1.0f / (float)NP);

#pragma unroll
        for (int e = 0; e < 4; e++) {
            float y = t[e] + shift;      // project onto hyperplane sum = K
            p[e] = -shift;               // p = t - y
            float u = y + q[e];
            float xn = fminf(fmaxf(u, 0.f), 1.f);  // project onto [0,1]
            q[e] = u - xn;
            x[e] = xn;
        }
    }
#pragma unroll
    for (int e = 0; e < 4; e++) g_mask[tid * 4 + e] = x[e];
}

// ---------------------------------------------------------------------------
// Kernel 2: materialize W[r][j] = mask[i] * V[i][j], i = (r-j) & 4095.
// Tile: 128 output rows x 32 cols. Needs V rows [r0-j0-31 .. r0-j0+127] (159
// rows) x 32 cols -> contiguous band, coalesced loads and writes.
// smem laid out stride-32 so the write-phase read bank is exactly jj
// (addr = (rr-jj+31)*32 + jj -> bank jj) : conflict-free.
// ---------------------------------------------------------------------------
#define WB_ROWS 128
#define WB_COLS 32
#define BAND_ALLOC 160   // 159 needed, round up

__global__ __launch_bounds__(256) void build_w_kernel(const float* __restrict__ V) {
    __shared__ float sV[BAND_ALLOC * WB_COLS];

    const int r0 = blockIdx.y * WB_ROWS;
    const int j0 = blockIdx.x * WB_COLS;
    const int i_min = (r0 - j0 - (WB_COLS - 1) + 2 * NP) & (NP - 1);
    const int tid = threadIdx.x;

    for (int idx = tid; idx < BAND_ALLOC * WB_COLS; idx += 256) {
        int t  = idx >> 5;
        int jj = idx & 31;
        int gi = (i_min + t) & (NP - 1);
        sV[idx] = g_mask[gi] * V[(size_t)gi * 4096 + j0 + jj];
    }
    __syncthreads();

    const int jj = tid & 31;
    const int rb = tid >> 5;  // 0..7
#pragma unroll
    for (int rr = rb; rr < WB_ROWS; rr += 8) {
        int toff = rr - jj + (WB_COLS - 1);          // in [0, 158]
        g_W[(size_t)(r0 + rr) * 4096 + j0 + jj] = sV[toff * 32 + jj];
    }
}

// ---------------------------------------------------------------------------
// Kernel 3: C[512,4096] = A[512,4096] * W^T  (NT fp32 GEMM)
// BM=BN=128, BK=16, 256 threads, 8x8 per-thread microtile, float4 I/O.
// ---------------------------------------------------------------------------
__global__ __launch_bounds__(256) void sgemm_kernel(const float* __restrict__ A,
                                                    float* __restrict__ C) {
    __shared__ float As[16][128];
    __shared__ float Bs[16][128];
    const float* __restrict__ B = g_W;

    const int n0 = blockIdx.x * 128;
    const int m0 = blockIdx.y * 128;
    const int tid = threadIdx.x;
    const int tx = tid & 15;
    const int ty = tid >> 4;
    const int lr = tid >> 2;          // 0..63
    const int lc = (tid & 3) << 2;    // 0,4,8,12

    const float* Aptr = A + (size_t)(m0 + lr) * 4096 + lc;
    const float* Bptr = B + (size_t)(n0 + lr) * 4096 + lc;

    float acc[8][8];
#pragma unroll
    for (int i = 0; i < 8; i++)
#pragma unroll
        for (int j = 0; j < 8; j++) acc[i][j] = 0.f;

    for (int k0 = 0; k0 < 4096; k0 += 16) {
        float4 a0 = *(const float4*)(Aptr + k0);
        float4 a1 = *(const float4*)(Aptr + k0 + (size_t)64 * 4096);
        float4 b0 = *(const float4*)(Bptr + k0);
        float4 b1 = *(const float4*)(Bptr + k0 + (size_t)64 * 4096);

        __syncthreads();   // protect previous iteration's smem reads

        As[lc + 0][lr] = a0.x; As[lc + 1][lr] = a0.y; As[lc + 2][lr] = a0.z; As[lc + 3][lr] = a0.w;
        As[lc + 0][lr + 64] = a1.x; As[lc + 1][lr + 64] = a1.y; As[lc + 2][lr + 64] = a1.z; As[lc + 3][lr + 64] = a1.w;
        Bs[lc + 0][lr] = b0.x; Bs[lc + 1][lr] = b0.y; Bs[lc + 2][lr] = b0.z; Bs[lc + 3][lr] = b0.w;
        Bs[lc + 0][lr + 64] = b1.x; Bs[lc + 1][lr + 64] = b1.y; Bs[lc + 2][lr + 64] = b1.z; Bs[lc + 3][lr + 64] = b1.w;

        __syncthreads();

#pragma unroll
        for (int kk = 0; kk < 16; kk++) {
            float4 af0 = *(const float4*)&As[kk][ty * 8];
            float4 af1 = *(const float4*)&As[kk][ty * 8 + 4];
            float4 bf0 = *(const float4*)&Bs[kk][tx * 8];
            float4 bf1 = *(const float4*)&Bs[kk][tx * 8 + 4];
            float af[8] = {af0.x, af0.y, af0.z, af0.w, af1.x, af1.y, af1.z, af1.w};
            float bf[8] = {bf0.x, bf0.y, bf0.z, bf0.w, bf1.x, bf1.y, bf1.z, bf1.w};
#pragma unroll
            for (int i = 0; i < 8; i++)
#pragma unroll
                for (int j = 0; j < 8; j++)
                    acc[i][j] = fmaf(af[i], bf[j], acc[i][j]);
        }
    }

#pragma unroll
    for (int i = 0; i < 8; i++) {
        float* Crow = C + (size_t)(m0 + ty * 8 + i) * 4096 + n0 + tx * 8;
        *(float4*)(Crow)     = make_float4(acc[i][0], acc[i][1], acc[i][2], acc[i][3]);
        *(float4*)(Crow + 4) = make_float4(acc[i][4], acc[i][5], acc[i][6], acc[i][7]);
    }
}

// ---------------------------------------------------------------------------
extern "C" void kernel_launch(void* const* d_in, const int* in_sizes, int n_in,
                              void* d_out, int out_size) {
    const float* x = nullptr;
    const float* V = nullptr;
    const float* alpha = nullptr;
    for (int i = 0; i < n_in; i++) {
        if (in_sizes[i] == 512 * 4096)       x     = (const float*)d_in[i];
        else if (in_sizes[i] == 4096 * 4096) V     = (const float*)d_in[i];
        else if (in_sizes[i] == 4096)        alpha = (const float*)d_in[i];
    }

    dykstra_kernel<<<1, 1024>>>(alpha);
    build_w_kernel<<<dim3(4096 / WB_COLS, 4096 / WB_ROWS), 256>>>(V);
    sgemm_kernel<<<dim3(4096 / 128, 512 / 128), 256>>>(x, (float*)d_out);
}

// round 3
// speedup vs baseline: 3.6889x; 3.6889x over previous
#include <cuda_runtime.h>

// ---------------------------------------------------------------------------
// Problem constants (IN = OUT = 4096, batch M = 512)
// ---------------------------------------------------------------------------
#define NP 4096
#define KTOP 3687.0f
#define INV_LR 100.0f
#define NUM_ITER 50

__device__ float g_mask[NP];
__device__ float g_W[(size_t)4096 * 4096];    // tf32-rounded W
__device__ float g_xr[(size_t)512 * 4096];    // tf32-rounded x

// ---------------------------------------------------------------------------
// Helpers
// ---------------------------------------------------------------------------
__device__ __forceinline__ unsigned f2tf32(float f) {
    unsigned u;
    asm("cvt.rna.tf32.f32 %0, %1;" : "=r"(u) : "f"(f));
    return u;
}
__device__ __forceinline__ unsigned smem_u32(const void* p) {
    unsigned a;
    asm("{ .reg .u64 t; cvta.to.shared.u64 t, %1; cvt.u32.u64 %0, t; }" : "=r"(a) : "l"(p));
    return a;
}
__device__ __forceinline__ void cp_async16(unsigned dst, const void* src) {
    asm volatile("cp.async.cg.shared.global [%0], [%1], 16;" :: "r"(dst), "l"(src));
}
__device__ __forceinline__ void mma_tf32(float* d, const unsigned* a, const unsigned* b) {
    asm volatile("mma.sync.aligned.m16n8k8.row.col.f32.tf32.tf32.f32 "
                 "{%0,%1,%2,%3}, {%4,%5,%6,%7}, {%8,%9}, {%0,%1,%2,%3};"
                 : "+f"(d[0]), "+f"(d[1]), "+f"(d[2]), "+f"(d[3])
                 : "r"(a[0]), "r"(a[1]), "r"(a[2]), "r"(a[3]), "r"(b[0]), "r"(b[1]));
}

// swizzled byte offset inside a [rows x 32 floats] tile: 16B chunk kq ^= row&7
#define TOFF(m, k) (((m) << 7) + (((((k) >> 2) ^ ((m) & 7))) << 4) + (((k) & 3) << 2))

// ---------------------------------------------------------------------------
// Kernel 0: round x to tf32 (once; removes truncation bias from the GEMM)
// ---------------------------------------------------------------------------
__global__ __launch_bounds__(256) void roundx_kernel(const float* __restrict__ x) {
    int i = blockIdx.x * 256 + threadIdx.x;   // one float4 per thread
    float4 v = ((const float4*)x)[i];
    uint4 o;
    o.x = f2tf32(v.x); o.y = f2tf32(v.y); o.z = f2tf32(v.z); o.w = f2tf32(v.w);
    ((uint4*)g_xr)[i] = o;
}

// ---------------------------------------------------------------------------
// Kernel 1: Dykstra soft-top-k mask (1024 threads, 1 barrier/iter)
// ---------------------------------------------------------------------------
__global__ __launch_bounds__(1024) void dykstra_kernel(const float* __restrict__ alpha) {
    __shared__ float red[2][32];
    int tid = threadIdx.x, lane = tid & 31, wid = tid >> 5;

    float x[4], p[4], q[4];
#pragma unroll
    for (int e = 0; e < 4; e++) {
        x[e] = alpha[tid * 4 + e] * INV_LR;
        p[e] = 0.f; q[e] = 0.f;
    }
    for (int it = 0; it < NUM_ITER; it++) {
        float t[4], local = 0.f;
#pragma unroll
        for (int e = 0; e < 4; e++) { t[e] = x[e] + p[e]; local += t[e]; }
#pragma unroll
        for (int o = 16; o > 0; o >>= 1) local += __shfl_xor_sync(0xffffffffu, local, o);
        int buf = it & 1;
        if (lane == 0) red[buf][wid] = local;
        __syncthreads();
        float v = red[buf][lane];
#pragma unroll
        for (int o = 16; o > 0; o >>= 1) v += __shfl_xor_sync(0xffffffffu, v, o);
        float shift = (KTOP - v) * (1.0f / (float)NP);
#pragma unroll
        for (int e = 0; e < 4; e++) {
            float y = t[e] + shift;
            p[e] = -shift;
            float u = y + q[e];
            float xn = fminf(fmaxf(u, 0.f), 1.f);
            q[e] = u - xn;
            x[e] = xn;
        }
    }
#pragma unroll
    for (int e = 0; e < 4; e++) g_mask[tid * 4 + e] = x[e];
}

// ---------------------------------------------------------------------------
// Kernel 2: W[r][j] = tf32_round(mask[(r-j)&4095] * V[(r-j)&4095][j])
// ---------------------------------------------------------------------------
#define WB_ROWS 128
#define WB_COLS 32
#define BAND_ALLOC 160

__global__ __launch_bounds__(256) void build_w_kernel(const float* __restrict__ V) {
    __shared__ float sV[BAND_ALLOC * WB_COLS];
    const int r0 = blockIdx.y * WB_ROWS;
    const int j0 = blockIdx.x * WB_COLS;
    const int i_min = (r0 - j0 - (WB_COLS - 1) + 2 * NP) & (NP - 1);
    const int tid = threadIdx.x;

    for (int idx = tid; idx < BAND_ALLOC * WB_COLS; idx += 256) {
        int t = idx >> 5, jj = idx & 31;
        int gi = (i_min + t) & (NP - 1);
        sV[idx] = g_mask[gi] * V[(size_t)gi * 4096 + j0 + jj];
    }
    __syncthreads();

    const int jj = tid & 31;
    const int rb = tid >> 5;
#pragma unroll
    for (int rr = rb; rr < WB_ROWS; rr += 8) {
        int toff = rr - jj + (WB_COLS - 1);
        g_W[(size_t)(r0 + rr) * 4096 + j0 + jj] = __uint_as_float(f2tf32(sV[toff * 32 + jj]));
    }
}

// ---------------------------------------------------------------------------
// Kernel 3: tf32 mma.sync GEMM  C[512,4096] = g_xr * g_W^T
//   BM=128 BN=128 BK=32, 4-stage cp.async, 4 warps x (64x64) tiles.
// ---------------------------------------------------------------------------
#define BM 128
#define BN 128
#define BK 32
#define STAGES 4
#define NCHUNK 128
#define STAGE_BYTES 32768          // A 16KB + B 16KB
#define SMEM_TOTAL (STAGES * STAGE_BYTES)

__global__ void __launch_bounds__(128, 1) mma_gemm_kernel(float* __restrict__ C) {
    extern __shared__ char smem[];
    const unsigned sbase = smem_u32(smem);
    const int tid = threadIdx.x;
    const int lane = tid & 31;
    const int warp = tid >> 5;
    const int m0 = blockIdx.y * BM;
    const int n0 = blockIdx.x * BN;
    const int wm = (warp >> 1) * 64;
    const int wn = (warp & 1) * 64;
    const int r = lane >> 2;       // 0..7
    const int c = lane & 3;        // 0..3

    const float* __restrict__ Ag = g_xr + (size_t)m0 * 4096;
    const float* __restrict__ Bg = g_W + (size_t)n0 * 4096;

    float acc[4][8][4];
#pragma unroll
    for (int mt = 0; mt < 4; mt++)
#pragma unroll
        for (int nt = 0; nt < 8; nt++)
#pragma unroll
            for (int e = 0; e < 4; e++) acc[mt][nt][e] = 0.f;

    // ---- loader lambda-ish macro: chunk cc into stage s ----
#define LOAD_CHUNK(cc)                                                            \
    do {                                                                          \
        const int s_ = (cc) & (STAGES - 1);                                       \
        const unsigned aB = sbase + s_ * STAGE_BYTES;                             \
        const unsigned bB = aB + 16384;                                           \
        const int kb = (cc) * BK;                                                 \
        _Pragma("unroll")                                                         \
        for (int i = 0; i < 8; i++) {                                             \
            int idx = tid + i * 128;                                              \
            int row = idx >> 3, u = idx & 7;                                      \
            unsigned sw = (unsigned)((row << 7) + ((u ^ (row & 7)) << 4));        \
            cp_async16(aB + sw, Ag + (size_t)row * 4096 + kb + u * 4);            \
            cp_async16(bB + sw, Bg + (size_t)row * 4096 + kb + u * 4);            \
        }                                                                         \
    } while (0)

    // prologue: stages 0..2
#pragma unroll
    for (int pc = 0; pc < STAGES - 1; pc++) {
        LOAD_CHUNK(pc);
        asm volatile("cp.async.commit_group;" ::: "memory");
    }

    for (int cc = 0; cc < NCHUNK; cc++) {
        asm volatile("cp.async.wait_group 2;" ::: "memory");
        __syncthreads();

        // issue next chunk (or empty group to keep the count constant)
        if (cc + STAGES - 1 < NCHUNK) LOAD_CHUNK(cc + STAGES - 1);
        asm volatile("cp.async.commit_group;" ::: "memory");

        // compute chunk cc from stage cc%4
        const char* As = smem + (cc & (STAGES - 1)) * STAGE_BYTES;
        const char* Bs = As + 16384;
#pragma unroll
        for (int ks = 0; ks < 4; ks++) {
            unsigned a[4][4], b[8][2];
            const int kc = ks * 8 + c;
#pragma unroll
            for (int mt = 0; mt < 4; mt++) {
                int m = wm + mt * 16 + r;
                a[mt][0] = *(const unsigned*)(As + TOFF(m, kc));
                a[mt][1] = *(const unsigned*)(As + TOFF(m + 8, kc));
                a[mt][2] = *(const unsigned*)(As + TOFF(m, kc + 4));
                a[mt][3] = *(const unsigned*)(As + TOFF(m + 8, kc + 4));
            }
#pragma unroll
            for (int nt = 0; nt < 8; nt++) {
                int n = wn + nt * 8 + (lane >> 2);
                b[nt][0] = *(const unsigned*)(Bs + TOFF(n, ks * 8 + c));
                b[nt][1] = *(const unsigned*)(Bs + TOFF(n, ks * 8 + c + 4));
            }
#pragma unroll
            for (int mt = 0; mt < 4; mt++)
#pragma unroll
                for (int nt = 0; nt < 8; nt++)
                    mma_tf32(acc[mt][nt], a[mt], b[nt]);
        }
    }

    // epilogue
#pragma unroll
    for (int mt = 0; mt < 4; mt++) {
        int row = m0 + wm + mt * 16 + r;
#pragma unroll
        for (int nt = 0; nt < 8; nt++) {
            int col = n0 + wn + nt * 8 + 2 * c;
            *(float2*)(C + (size_t)row * 4096 + col) = make_float2(acc[mt][nt][0], acc[mt][nt][1]);
            *(float2*)(C + (size_t)(row + 8) * 4096 + col) = make_float2(acc[mt][nt][2], acc[mt][nt][3]);
        }
    }
#undef LOAD_CHUNK
}

// ---------------------------------------------------------------------------
extern "C" void kernel_launch(void* const* d_in, const int* in_sizes, int n_in,
                              void* d_out, int out_size) {
    const float* x = nullptr;
    const float* V = nullptr;
    const float* alpha = nullptr;
    for (int i = 0; i < n_in; i++) {
        if (in_sizes[i] == 512 * 4096)       x     = (const float*)d_in[i];
        else if (in_sizes[i] == 4096 * 4096) V     = (const float*)d_in[i];
        else if (in_sizes[i] == 4096)        alpha = (const float*)d_in[i];
    }

    cudaFuncSetAttribute(mma_gemm_kernel, cudaFuncAttributeMaxDynamicSharedMemorySize, SMEM_TOTAL);

    dykstra_kernel<<<1, 1024>>>(alpha);
    roundx_kernel<<<512 * 4096 / 4 / 256, 256>>>(x);
    build_w_kernel<<<dim3(4096 / WB_COLS, 4096 / WB_ROWS), 256>>>(V);
    mma_gemm_kernel<<<dim3(4096 / BN, 512 / BM), 128, SMEM_TOTAL>>>((float*)d_out);
}